// round 14
// baseline (speedup 1.0000x reference)
#include <cuda_runtime.h>
#include <cuda_fp16.h>
#include <cstdint>

#define L    16
#define NB   128
#define NC   128
#define NE   10
#define NT3  816
#define NT3P 832      // padded to 13*64
#define NT2  136
#define COLS2 24
#define NWY  68
#define NCHUNK 13     // K chunks of 64

typedef unsigned long long ull;

// ---------------- device globals ----------------
__device__ unsigned g_idx3[NT3];
__device__ float    g_wy[NB * NWY * NC];
// fp16 coefficient chunk images, row-major: [chunk][j=128][t_in=64]
__device__ __align__(16) __half g_B3hi[NCHUNK * 8192];

// ---------------- helpers ----------------
__device__ __forceinline__ uint32_t smem_u32(const void* p) {
    uint32_t a;
    asm("{ .reg .u64 t; cvta.to.shared.u64 t, %1; cvt.u32.u64 %0, t; }" : "=r"(a) : "l"(p));
    return a;
}
__device__ __forceinline__ ull pack2(float v) {
    ull r; asm("mov.b64 %0, {%1, %1};" : "=l"(r) : "f"(v)); return r;
}
__device__ __forceinline__ void unpack2(ull v, float& lo, float& hi) {
    asm("mov.b64 {%0, %1}, %2;" : "=f"(lo), "=f"(hi) : "l"(v));
}
__device__ __forceinline__ void fma2(ull& d, ull a, ull b) {
    asm("fma.rn.f32x2 %0, %1, %2, %0;" : "+l"(d) : "l"(a), "l"(b));
}
__device__ __forceinline__ void ldsm4(uint32_t* r, uint32_t addr) {
    asm volatile("ldmatrix.sync.aligned.m8n8.x4.shared.b16 {%0,%1,%2,%3}, [%4];"
                 : "=r"(r[0]), "=r"(r[1]), "=r"(r[2]), "=r"(r[3]) : "r"(addr));
}
__device__ __forceinline__ void mma16816h(float* d, const uint32_t* a,
                                          uint32_t b0, uint32_t b1) {
    asm volatile("mma.sync.aligned.m16n8k16.row.col.f32.f16.f16.f32 "
                 "{%0,%1,%2,%3}, {%4,%5,%6,%7}, {%8,%9}, {%0,%1,%2,%3};"
                 : "+f"(d[0]), "+f"(d[1]), "+f"(d[2]), "+f"(d[3])
                 : "r"(a[0]), "r"(a[1]), "r"(a[2]), "r"(a[3]), "r"(b0), "r"(b1));
}
__device__ __forceinline__ void cp16(uint32_t daddr, const void* gsrc) {
    asm volatile("cp.async.cg.shared.global [%0], [%1], 16;"
                 :: "r"(daddr), "l"(gsrc) : "memory");
}
#define CP_COMMIT() asm volatile("cp.async.commit_group;" ::: "memory")
#define CP_WAIT0()  asm volatile("cp.async.wait_group 0;" ::: "memory")

// ---------------- K0: order-3 symmetrize + fp16 quantize ----------------
// grid = 208 x 512: block handles 4 triples, thread = (t, j).
__global__ void __launch_bounds__(512) k_setup3(const float* __restrict__ U3_0e,
                                                const float* __restrict__ U3_1o) {
    int t = blockIdx.x * 4 + (threadIdx.x >> 7);
    int j = threadIdx.x & 127;
    float val = 0.f;
    if (t < NT3) {
        int rem = t, A = 0, B = 0, D = 0;
        {
            int i = 0;
            for (;;) { int m = L - i; int cnt = m * (m + 1) / 2;
                       if (rem < cnt) break; rem -= cnt; i++; }
            A = i;
            int q = A;
            for (;;) { int cnt = L - q;
                       if (rem < cnt) break; rem -= cnt; q++; }
            B = q; D = B + rem;
        }
        if (j == 0) g_idx3[t] = (unsigned)A | ((unsigned)B << 8) | ((unsigned)D << 16);
        int P[6][3] = {{A,B,D},{A,D,B},{B,A,D},{B,D,A},{D,A,B},{D,B,A}};
        if (j < 122) {
            for (int i = 0; i < 6; i++) {
                bool dup = false;
                for (int q = 0; q < i; q++)
                    if (P[q][0] == P[i][0] && P[q][1] == P[i][1] && P[q][2] == P[i][2]) dup = true;
                if (dup) continue;
                int p0 = P[i][0], p1 = P[i][1], p2 = P[i][2];
                if (j < 23) {
                    val += U3_0e[((p0 * L + p1) * L + p2) * 23 + j];
                } else {
                    int w = (j - 23) / 33, k = (j - 23) % 33;
                    val += U3_1o[(((w * L + p0) * L + p1) * L + p2) * 33 + k];
                }
            }
        }
    }
    g_B3hi[(t >> 6) * 8192 + j * 64 + (t & 63)] = __float2half_rn(val);
}

// ---------------- K1: wy + order-1/2 + output base (self-contained) -------
// Launched FIRST (no dependency on k_setup3).
__global__ void __launch_bounds__(256) k_wy(
        const float* __restrict__ y, const float* __restrict__ x,
        const float* __restrict__ w3_0e, const float* __restrict__ w3_1o,
        const float* __restrict__ w2_0e, const float* __restrict__ w2_1o,
        const float* __restrict__ w1_0e, const float* __restrict__ w1_1o,
        const float* __restrict__ U1_0e, const float* __restrict__ U2_0e,
        const float* __restrict__ U1_1o, const float* __restrict__ U2_1o,
        float* __restrict__ out) {
    __shared__ __align__(16) float ys[NE];
    __shared__ __align__(16) float Xs[NC * 17];
    __shared__ __align__(16) float wys[12 * NC];
    __shared__ __align__(16) float Us2s[NT2 * COLS2];
    __shared__ __align__(16) float Us1s[L * 4];
    __shared__ __align__(16) float red2[NC * 4 * 2];
    __shared__ unsigned sIdx2[NT2];
    const int tid = threadIdx.x;
    const int b = blockIdx.x;

    if (tid < NE) ys[tid] = y[b * NE + tid];
    if (tid < L * 4) {
        int a = tid >> 2, col = tid & 3;
        Us1s[tid] = (col == 0) ? U1_0e[a] : U1_1o[(col - 1) * L + a];
    }
    {
        int c = tid >> 1, off = (tid & 1) * 8;
        const float4* xp = (const float4*)(x + (b * NC + c) * L + off);
        float4 v0 = xp[0], v1 = xp[1];
        float* dst = Xs + c * 17 + off;
        dst[0] = v0.x; dst[1] = v0.y; dst[2] = v0.z; dst[3] = v0.w;
        dst[4] = v1.x; dst[5] = v1.y; dst[6] = v1.z; dst[7] = v1.w;
    }
    // decode sorted pairs
    for (int i = tid; i < NT2; i += 256) {
        int rem = i, A = 0;
        for (;;) { int cnt = L - A; if (rem < cnt) break; rem -= cnt; A++; }
        sIdx2[i] = (unsigned)A | ((unsigned)(A + rem) << 8);
    }
    __syncthreads();

    // symmetrized order-2 table (inline from U2 tensors)
    for (int i = tid; i < NT2 * 22; i += 256) {
        int t = i / 22, j = i - t * 22;
        unsigned u = sIdx2[t];
        int A = u & 255, B = (u >> 8) & 255;
        float val;
        if (j < 4) {
            val = U2_0e[(A * L + B) * 4 + j];
            if (A != B) val += U2_0e[(B * L + A) * 4 + j];
        } else {
            int w = (j - 4) / 6, k = (j - 4) % 6;
            val = U2_1o[((w * L + A) * L + B) * 6 + k];
            if (A != B) val += U2_1o[((w * L + B) * L + A) * 6 + k];
        }
        Us2s[t * COLS2 + j] = val;
    }

    // wy[b][jw][c]
    for (int idx = tid; idx < NWY * NC; idx += 256) {
        int jw = idx >> 7, c = idx & 127;
        const float* wsrc; int K, k;
        if (jw < 23)       { wsrc = w3_0e; K = 23; k = jw; }
        else if (jw < 56)  { wsrc = w3_1o; K = 33; k = jw - 23; }
        else if (jw < 60)  { wsrc = w2_0e; K = 4;  k = jw - 56; }
        else if (jw < 66)  { wsrc = w2_1o; K = 6;  k = jw - 60; }
        else if (jw == 66) { wsrc = w1_0e; K = 1;  k = 0; }
        else               { wsrc = w1_1o; K = 1;  k = 0; }
        float acc = 0.f;
#pragma unroll
        for (int e = 0; e < NE; e++)
            acc = fmaf(wsrc[(e * K + k) * NC + c], ys[e], acc);
        g_wy[(b * NWY + jw) * NC + c] = acc;
        if (jw >= 56) wys[(jw - 56) * NC + c] = acc;
    }
    __syncthreads();

    const int c = tid & 127;
    const int half = tid >> 7;
    const float* Xc = Xs + c * 17;
    ull P2[11];
#pragma unroll
    for (int k = 0; k < 11; k++) P2[k] = 0ull;
    for (int t = half * 68; t < half * 68 + 68; t++) {
        unsigned u = sIdx2[t];
        ull m2 = pack2(Xc[u & 255] * Xc[(u >> 8) & 255]);
        const ull* row = (const ull*)(Us2s + t * COLS2);
#pragma unroll
        for (int k = 0; k < 11; k++) fma2(P2[k], m2, row[k]);
    }
    float contrib[4] = {0.f, 0.f, 0.f, 0.f};
#pragma unroll
    for (int k = 0; k < 11; k++) {
        float lo, hi;
        unpack2(P2[k], lo, hi);
#pragma unroll
        for (int hh = 0; hh < 2; hh++) {
            int j = 2 * k + hh;
            float v = (hh == 0) ? lo : hi;
            int tgt, row;
            if (j < 4) { tgt = 0; row = j; }
            else { int wq = (j - 4) / 6; tgt = 1 + wq; row = 4 + (j - 4 - wq * 6); }
            contrib[tgt] += v * wys[row * NC + c];
        }
    }
    if (half == 0) {
        float P0 = 0.f, P1 = 0.f, Pq = 0.f, P3 = 0.f;
#pragma unroll
        for (int a = 0; a < L; a++) {
            float xa = Xc[a];
            P0 = fmaf(Us1s[a * 4 + 0], xa, P0);
            P1 = fmaf(Us1s[a * 4 + 1], xa, P1);
            Pq = fmaf(Us1s[a * 4 + 2], xa, Pq);
            P3 = fmaf(Us1s[a * 4 + 3], xa, P3);
        }
        contrib[0] = fmaf(P0, wys[10 * NC + c], contrib[0]);
        contrib[1] = fmaf(P1, wys[11 * NC + c], contrib[1]);
        contrib[2] = fmaf(Pq, wys[11 * NC + c], contrib[2]);
        contrib[3] = fmaf(P3, wys[11 * NC + c], contrib[3]);
    }
#pragma unroll
    for (int tgt = 0; tgt < 4; tgt++)
        red2[(c * 4 + tgt) * 2 + half] = contrib[tgt];
    __syncthreads();
    for (int i = tid; i < 512; i += 256) {
        int cc = i >> 2, tgt = i & 3;
        float v = red2[i * 2] + red2[i * 2 + 1];
        if (tgt == 0) out[b * 512 + cc] = v;
        else out[b * 512 + 128 + 3 * cc + (tgt - 1)] = v;
    }
}

// ---------------- K2: order-3 HMMA fp16, 1-term, fused pipeline ------------
// grid = 256: (atom b, K-half kh). 8 warps = 4 row-groups x 2 col-groups.
// smem: A0 16K | A1 16K | B0 16K | B1 16K | Xs 8.5K | idx 3.3K  = 77568
#define OFF_A0   0
#define OFF_A1   16384
#define OFF_B0   32768
#define OFF_B1   49152
#define OFF_XS   65536
#define OFF_IDX  74240
#define SMEM_TOTAL 77568

__global__ void __launch_bounds__(256, 2) k_main(const float* __restrict__ x,
                                                 float* __restrict__ out) {
    extern __shared__ __align__(1024) char smc[];
    const uint32_t sb = smem_u32(smc);
    const int tid = threadIdx.x;
    const int wid = tid >> 5;
    const int lane = tid & 31;
    const int b = blockIdx.x >> 1;
    const int kh = blockIdx.x & 1;
    const int q0 = kh ? 7 : 0;
    const int q1 = kh ? NCHUNK : 7;

    float* Xs = (float*)(smc + OFF_XS);
    unsigned* sIdx = (unsigned*)(smc + OFF_IDX);   // NT3P entries (padded)

    // prologue: stream B(q0), stage X + idx
    {
        const char* srcH = (const char*)g_B3hi + q0 * 16384;
        for (int i = tid; i < 1024; i += 256) {
            int row = i >> 3, u = i & 7;
            uint32_t doff = (uint32_t)(row * 128 + ((u ^ (row & 7)) << 4));
            int soff = (row * 64 + u * 8) * 2;
            cp16(sb + OFF_B0 + doff, srcH + soff);
        }
        CP_COMMIT();
    }
    {
        int c = tid >> 1, off = (tid & 1) * 8;
        const float4* xp = (const float4*)(x + (b * NC + c) * L + off);
        float4 v0 = xp[0], v1 = xp[1];
        float* dst = Xs + c * 17 + off;
        dst[0] = v0.x; dst[1] = v0.y; dst[2] = v0.z; dst[3] = v0.w;
        dst[4] = v1.x; dst[5] = v1.y; dst[6] = v1.z; dst[7] = v1.w;
    }
    for (int i = tid; i < NT3P; i += 256) sIdx[i] = (i < NT3) ? g_idx3[i] : 0u;
    __syncthreads();                       // Xs/idx ready for build

    // build A(q0) -> A0
    for (int item = tid; item < 1024; item += 256) {
        int c = item & 127, u = item >> 7;
        const float* Xc = Xs + c * 17;
        const uint4* ip = (const uint4*)(sIdx + q0 * 64 + u * 8);
        uint4 i0 = ip[0], i1 = ip[1];
        unsigned uu[8] = {i0.x, i0.y, i0.z, i0.w, i1.x, i1.y, i1.z, i1.w};
        float m[8];
#pragma unroll
        for (int e = 0; e < 8; e++) {
            int gt = q0 * 64 + u * 8 + e;
            m[e] = (gt < NT3)
                 ? Xc[uu[e] & 255] * Xc[(uu[e] >> 8) & 255] * Xc[(uu[e] >> 16) & 255]
                 : 0.f;
        }
        uint32_t h[4];
#pragma unroll
        for (int p = 0; p < 4; p++) {
            __half2 hp = __floats2half2_rn(m[2 * p], m[2 * p + 1]);
            h[p] = *(uint32_t*)&hp;
        }
        uint32_t doff = (uint32_t)(c * 128 + ((u ^ (c & 7)) << 4));
        *(uint4*)(smc + OFF_A0 + doff) = make_uint4(h[0], h[1], h[2], h[3]);
    }
    CP_WAIT0();
    __syncthreads();                       // A(q0) + B(q0) visible to all

    float acc[16][4];
#pragma unroll
    for (int nt = 0; nt < 16; nt++)
#pragma unroll
        for (int k = 0; k < 4; k++) acc[nt][k] = 0.f;

    const int rw = wid & 3, cw = wid >> 2;
    const int R0 = rw * 32, C0 = cw * 64;
    const int mat = lane >> 3, lr = lane & 7;
    const int g = lane >> 2;

    for (int i = 0, q = q0; q < q1; ++i, ++q) {
        const uint32_t bufA = (i & 1) ? OFF_A1 : OFF_A0;
        const uint32_t bufAn = (i & 1) ? OFF_A0 : OFF_A1;
        const uint32_t bufB = (i & 1) ? OFF_B1 : OFF_B0;
        const uint32_t bufBn = (i & 1) ? OFF_B0 : OFF_B1;

        if (q + 1 < q1) {
            // stream B(q+1) into alternate buffer
            const char* srcH = (const char*)g_B3hi + (q + 1) * 16384;
            for (int ii = tid; ii < 1024; ii += 256) {
                int row = ii >> 3, u = ii & 7;
                uint32_t doff = (uint32_t)(row * 128 + ((u ^ (row & 7)) << 4));
                int soff = (row * 64 + u * 8) * 2;
                cp16(sb + bufBn + doff, srcH + soff);
            }
            CP_COMMIT();
            // build A(q+1) into alternate buffer -- overlaps MMA(q)
            for (int item = tid; item < 1024; item += 256) {
                int c = item & 127, u = item >> 7;
                const float* Xc = Xs + c * 17;
                const uint4* ip = (const uint4*)(sIdx + (q + 1) * 64 + u * 8);
                uint4 i0 = ip[0], i1 = ip[1];
                unsigned uu[8] = {i0.x, i0.y, i0.z, i0.w, i1.x, i1.y, i1.z, i1.w};
                float m[8];
#pragma unroll
                for (int e = 0; e < 8; e++) {
                    int gt = (q + 1) * 64 + u * 8 + e;
                    m[e] = (gt < NT3)
                         ? Xc[uu[e] & 255] * Xc[(uu[e] >> 8) & 255] * Xc[(uu[e] >> 16) & 255]
                         : 0.f;
                }
                uint32_t h[4];
#pragma unroll
                for (int p = 0; p < 4; p++) {
                    __half2 hp = __floats2half2_rn(m[2 * p], m[2 * p + 1]);
                    h[p] = *(uint32_t*)&hp;
                }
                uint32_t doff = (uint32_t)(c * 128 + ((u ^ (c & 7)) << 4));
                *(uint4*)(smc + bufAn + doff) = make_uint4(h[0], h[1], h[2], h[3]);
            }
        }

        // MMA(q): 4 k-steps; warp tile 32 rows x 64 cols; single fp16 term
#pragma unroll
        for (int s = 0; s < 4; s++) {
            const int u0 = s * 2;
            uint32_t ah0[4], ah1[4];
            {
                int arow = R0 + lr + (mat & 1) * 8;
                int au = u0 + (mat >> 1);
                ldsm4(ah0, sb + bufA + (uint32_t)(arow * 128 + ((au ^ (arow & 7)) << 4)));
                int arow1 = arow + 16;
                ldsm4(ah1, sb + bufA + (uint32_t)(arow1 * 128 + ((au ^ (arow1 & 7)) << 4)));
            }
#pragma unroll
            for (int p = 0; p < 4; p++) {
                int brow = C0 + p * 16 + (mat >> 1) * 8 + lr;
                int bu = u0 + (mat & 1);
                uint32_t boff = (uint32_t)(brow * 128 + ((bu ^ (brow & 7)) << 4));
                uint32_t bh[4];
                ldsm4(bh, sb + bufB + boff);
                mma16816h(acc[p * 2],         ah0, bh[0], bh[1]);
                mma16816h(acc[p * 2 + 1],     ah0, bh[2], bh[3]);
                mma16816h(acc[8 + p * 2],     ah1, bh[0], bh[1]);
                mma16816h(acc[8 + p * 2 + 1], ah1, bh[2], bh[3]);
            }
        }
        CP_WAIT0();        // B(q+1) landed (own thread's copies)
        __syncthreads();   // A(q+1)/B(q+1) ready; MMA(q) done reading buffers
    }

    // ===== epilogue: weight by wy, reduce cols (shfl) + col-groups (smem) ====
    float* red = (float*)(smc + OFF_A0);   // alias A0 (free after loop + sync)
    const float* wyb = g_wy + b * NWY * NC;
    float ct[4][4];
#pragma unroll
    for (int a = 0; a < 4; a++)
#pragma unroll
        for (int t = 0; t < 4; t++) ct[a][t] = 0.f;
#pragma unroll
    for (int mi = 0; mi < 2; mi++) {
        int ra = R0 + mi * 16 + g;
        int rb = ra + 8;
#pragma unroll
        for (int ni = 0; ni < 8; ni++) {
#pragma unroll
            for (int hh = 0; hh < 2; hh++) {
                int j = C0 + ni * 8 + 2 * (lane & 3) + hh;
                if (j < 122) {
                    int tgt, wyc;
                    if (j < 23) { tgt = 0; wyc = j; }
                    else { int wq = (j - 23) / 33; tgt = 1 + wq; wyc = 23 + (j - 23 - wq * 33); }
                    ct[mi * 2 + 0][tgt] += acc[mi * 8 + ni][hh]     * wyb[wyc * NC + ra];
                    ct[mi * 2 + 1][tgt] += acc[mi * 8 + ni][2 + hh] * wyb[wyc * NC + rb];
                }
            }
        }
    }
#pragma unroll
    for (int a = 0; a < 4; a++)
#pragma unroll
        for (int t = 0; t < 4; t++) {
            ct[a][t] += __shfl_xor_sync(0xffffffffu, ct[a][t], 1);
            ct[a][t] += __shfl_xor_sync(0xffffffffu, ct[a][t], 2);
        }
    if ((lane & 3) == 0) {
#pragma unroll
        for (int mi = 0; mi < 2; mi++) {
            int ra = R0 + mi * 16 + g;
#pragma unroll
            for (int t = 0; t < 4; t++) {
                red[(cw * 128 + ra) * 4 + t]     = ct[mi * 2 + 0][t];
                red[(cw * 128 + ra + 8) * 4 + t] = ct[mi * 2 + 1][t];
            }
        }
    }
    __syncthreads();
    for (int i = tid; i < 512; i += 256) {
        int row = i >> 2, tgt = i & 3;
        float v = red[row * 4 + tgt] + red[(128 + row) * 4 + tgt];
        float* ob = out + b * 512;
        if (tgt == 0) atomicAdd(&ob[row], v);
        else atomicAdd(&ob[128 + 3 * row + (tgt - 1)], v);
    }
}

extern "C" void kernel_launch(void* const* d_in, const int* in_sizes, int n_in,
                              void* d_out, int out_size) {
    const float* x      = (const float*)d_in[0];
    const float* y      = (const float*)d_in[1];
    const float* U1_0e  = (const float*)d_in[2];
    const float* U2_0e  = (const float*)d_in[3];
    const float* U3_0e  = (const float*)d_in[4];
    const float* U1_1o  = (const float*)d_in[5];
    const float* U2_1o  = (const float*)d_in[6];
    const float* U3_1o  = (const float*)d_in[7];
    const float* w1_0e  = (const float*)d_in[8];
    const float* w2_0e  = (const float*)d_in[9];
    const float* w3_0e  = (const float*)d_in[10];
    const float* w1_1o  = (const float*)d_in[11];
    const float* w2_1o  = (const float*)d_in[12];
    const float* w3_1o  = (const float*)d_in[13];
    float* out = (float*)d_out;

    cudaFuncSetAttribute(k_main, cudaFuncAttributeMaxDynamicSharedMemorySize, SMEM_TOTAL);

    k_wy<<<NB, 256>>>(y, x, w3_0e, w3_1o, w2_0e, w2_1o, w1_0e, w1_1o,
                      U1_0e, U2_0e, U1_1o, U2_1o, out);
    k_setup3<<<(NT3P + 3) / 4, 512>>>(U3_0e, U3_1o);
    k_main<<<2 * NB, 256, SMEM_TOTAL>>>(x, out);
}

// round 15
// speedup vs baseline: 1.1774x; 1.1774x over previous
#include <cuda_runtime.h>
#include <cuda_fp16.h>
#include <cstdint>

#define L    16
#define NB   128
#define NC   128
#define NE   10
#define NT3  816
#define NT3P 832      // padded to 13*64
#define NT2  136
#define COLS2 24
#define NWY  68
#define NCHUNK 13     // K chunks of 64

typedef unsigned long long ull;

// ---------------- device globals ----------------
__device__ unsigned g_idx3[NT3];
__device__ __align__(16) float g_Us2[NT2 * COLS2];
__device__ float    g_Us1[L * 4];
__device__ float    g_wy[NB * NWY * NC];
// fp16 coefficient chunk images, row-major: [chunk][j=128][t_in=64]
__device__ __align__(16) __half g_B3hi[NCHUNK * 8192];

// ---------------- helpers ----------------
__device__ __forceinline__ uint32_t smem_u32(const void* p) {
    uint32_t a;
    asm("{ .reg .u64 t; cvta.to.shared.u64 t, %1; cvt.u32.u64 %0, t; }" : "=r"(a) : "l"(p));
    return a;
}
__device__ __forceinline__ ull pack2(float v) {
    ull r; asm("mov.b64 %0, {%1, %1};" : "=l"(r) : "f"(v)); return r;
}
__device__ __forceinline__ void unpack2(ull v, float& lo, float& hi) {
    asm("mov.b64 {%0, %1}, %2;" : "=f"(lo), "=f"(hi) : "l"(v));
}
__device__ __forceinline__ void fma2(ull& d, ull a, ull b) {
    asm("fma.rn.f32x2 %0, %1, %2, %0;" : "+l"(d) : "l"(a), "l"(b));
}
__device__ __forceinline__ void ldsm4(uint32_t* r, uint32_t addr) {
    asm volatile("ldmatrix.sync.aligned.m8n8.x4.shared.b16 {%0,%1,%2,%3}, [%4];"
                 : "=r"(r[0]), "=r"(r[1]), "=r"(r[2]), "=r"(r[3]) : "r"(addr));
}
__device__ __forceinline__ void mma16816h(float* d, const uint32_t* a,
                                          uint32_t b0, uint32_t b1) {
    asm volatile("mma.sync.aligned.m16n8k16.row.col.f32.f16.f16.f32 "
                 "{%0,%1,%2,%3}, {%4,%5,%6,%7}, {%8,%9}, {%0,%1,%2,%3};"
                 : "+f"(d[0]), "+f"(d[1]), "+f"(d[2]), "+f"(d[3])
                 : "r"(a[0]), "r"(a[1]), "r"(a[2]), "r"(a[3]), "r"(b0), "r"(b1));
}
__device__ __forceinline__ void cp16(uint32_t daddr, const void* gsrc) {
    asm volatile("cp.async.cg.shared.global [%0], [%1], 16;"
                 :: "r"(daddr), "l"(gsrc) : "memory");
}
#define CP_COMMIT() asm volatile("cp.async.commit_group;" ::: "memory")
#define CP_WAIT0()  asm volatile("cp.async.wait_group 0;" ::: "memory")

// ---------------- K0: merged pre-pass ----------------
// grid = 337 x 512:
//   blocks [0,208):   order-3 symmetrize + fp16 (4 triples/block)
//   blocks [208,336): wy GEMM for atom b = blk-208  + zero out[b]
//   block  336:       order-2 symmetrized table + order-1 table
__global__ void __launch_bounds__(512) k_pre(
        const float* __restrict__ y,
        const float* __restrict__ U1_0e, const float* __restrict__ U2_0e,
        const float* __restrict__ U3_0e, const float* __restrict__ U1_1o,
        const float* __restrict__ U2_1o, const float* __restrict__ U3_1o,
        const float* __restrict__ w1_0e, const float* __restrict__ w2_0e,
        const float* __restrict__ w3_0e, const float* __restrict__ w1_1o,
        const float* __restrict__ w2_1o, const float* __restrict__ w3_1o,
        float* __restrict__ out) {
    const int blk = blockIdx.x;
    const int tid = threadIdx.x;
    if (blk < 208) {
        int t = blk * 4 + (tid >> 7);
        int j = tid & 127;
        float val = 0.f;
        if (t < NT3) {
            int rem = t, A = 0, B = 0, D = 0;
            {
                int i = 0;
                for (;;) { int m = L - i; int cnt = m * (m + 1) / 2;
                           if (rem < cnt) break; rem -= cnt; i++; }
                A = i;
                int q = A;
                for (;;) { int cnt = L - q;
                           if (rem < cnt) break; rem -= cnt; q++; }
                B = q; D = B + rem;
            }
            if (j == 0) g_idx3[t] = (unsigned)A | ((unsigned)B << 8) | ((unsigned)D << 16);
            int P[6][3] = {{A,B,D},{A,D,B},{B,A,D},{B,D,A},{D,A,B},{D,B,A}};
            if (j < 122) {
                for (int i = 0; i < 6; i++) {
                    bool dup = false;
                    for (int q = 0; q < i; q++)
                        if (P[q][0] == P[i][0] && P[q][1] == P[i][1] && P[q][2] == P[i][2]) dup = true;
                    if (dup) continue;
                    int p0 = P[i][0], p1 = P[i][1], p2 = P[i][2];
                    if (j < 23) {
                        val += U3_0e[((p0 * L + p1) * L + p2) * 23 + j];
                    } else {
                        int w = (j - 23) / 33, k = (j - 23) % 33;
                        val += U3_1o[(((w * L + p0) * L + p1) * L + p2) * 33 + k];
                    }
                }
            }
        }
        if (t < NT3P)
            g_B3hi[(t >> 6) * 8192 + j * 64 + (t & 63)] = __float2half_rn(val);
    } else if (blk < 336) {
        const int b = blk - 208;
        __shared__ float ys[NE];
        if (tid < NE) ys[tid] = y[b * NE + tid];
        out[b * 512 + tid] = 0.f;                    // zero base (512 threads)
        __syncthreads();
        for (int idx = tid; idx < NWY * NC; idx += 512) {
            int jw = idx >> 7, c = idx & 127;
            const float* wsrc; int K, k;
            if (jw < 23)       { wsrc = w3_0e; K = 23; k = jw; }
            else if (jw < 56)  { wsrc = w3_1o; K = 33; k = jw - 23; }
            else if (jw < 60)  { wsrc = w2_0e; K = 4;  k = jw - 56; }
            else if (jw < 66)  { wsrc = w2_1o; K = 6;  k = jw - 60; }
            else if (jw == 66) { wsrc = w1_0e; K = 1;  k = 0; }
            else               { wsrc = w1_1o; K = 1;  k = 0; }
            float acc = 0.f;
#pragma unroll
            for (int e = 0; e < NE; e++)
                acc = fmaf(wsrc[(e * K + k) * NC + c], ys[e], acc);
            g_wy[(b * NWY + jw) * NC + c] = acc;
        }
    } else {
        // symmetrized order-2 table + order-1 table
        for (int i = tid; i < NT2 * COLS2; i += 512) {
            int t = i / COLS2, j = i - t * COLS2;
            int rem = t, A = 0;
            for (;;) { int cnt = L - A; if (rem < cnt) break; rem -= cnt; A++; }
            int Bp = A + rem;
            float val = 0.f;
            if (j < 22) {
                if (j < 4) {
                    val = U2_0e[(A * L + Bp) * 4 + j];
                    if (A != Bp) val += U2_0e[(Bp * L + A) * 4 + j];
                } else {
                    int w = (j - 4) / 6, k = (j - 4) % 6;
                    val = U2_1o[((w * L + A) * L + Bp) * 6 + k];
                    if (A != Bp) val += U2_1o[((w * L + Bp) * L + A) * 6 + k];
                }
            }
            g_Us2[i] = val;
        }
        if (tid < L * 4) {
            int a = tid >> 2, col = tid & 3;
            g_Us1[tid] = (col == 0) ? U1_0e[a] : U1_1o[(col - 1) * L + a];
        }
    }
}

// ---------------- K2: order-3 HMMA + (kh==1) order-1/2 tail ---------------
// grid = 256: (atom b, K-half kh). 8 warps = 4 row-groups x 2 col-groups.
// smem: A0 16K | A1 16K | B0 16K | B1 16K | Xs 8.5K | idx 3.3K  = 77568
#define OFF_A0   0
#define OFF_A1   16384
#define OFF_B0   32768
#define OFF_B1   49152
#define OFF_XS   65536
#define OFF_IDX  74240
#define SMEM_TOTAL 77568

__global__ void __launch_bounds__(256, 2) k_main(const float* __restrict__ x,
                                                 float* __restrict__ out) {
    extern __shared__ __align__(1024) char smc[];
    const uint32_t sb = smem_u32(smc);
    const int tid = threadIdx.x;
    const int wid = tid >> 5;
    const int lane = tid & 31;
    const int b = blockIdx.x >> 1;
    const int kh = blockIdx.x & 1;
    const int q0 = kh ? 7 : 0;
    const int q1 = kh ? NCHUNK : 7;

    float* Xs = (float*)(smc + OFF_XS);
    unsigned* sIdx = (unsigned*)(smc + OFF_IDX);   // NT3P entries (padded)

    // prologue: stream B(q0), stage X + idx
    {
        const char* srcH = (const char*)g_B3hi + q0 * 16384;
        for (int i = tid; i < 1024; i += 256) {
            int row = i >> 3, u = i & 7;
            uint32_t doff = (uint32_t)(row * 128 + ((u ^ (row & 7)) << 4));
            int soff = (row * 64 + u * 8) * 2;
            cp16(sb + OFF_B0 + doff, srcH + soff);
        }
        CP_COMMIT();
    }
    {
        int c = tid >> 1, off = (tid & 1) * 8;
        const float4* xp = (const float4*)(x + (b * NC + c) * L + off);
        float4 v0 = xp[0], v1 = xp[1];
        float* dst = Xs + c * 17 + off;
        dst[0] = v0.x; dst[1] = v0.y; dst[2] = v0.z; dst[3] = v0.w;
        dst[4] = v1.x; dst[5] = v1.y; dst[6] = v1.z; dst[7] = v1.w;
    }
    for (int i = tid; i < NT3P; i += 256) sIdx[i] = (i < NT3) ? g_idx3[i] : 0u;
    __syncthreads();                       // Xs/idx ready for build

    // build A(q0) -> A0
    for (int item = tid; item < 1024; item += 256) {
        int c = item & 127, u = item >> 7;
        const float* Xc = Xs + c * 17;
        const uint4* ip = (const uint4*)(sIdx + q0 * 64 + u * 8);
        uint4 i0 = ip[0], i1 = ip[1];
        unsigned uu[8] = {i0.x, i0.y, i0.z, i0.w, i1.x, i1.y, i1.z, i1.w};
        float m[8];
#pragma unroll
        for (int e = 0; e < 8; e++) {
            int gt = q0 * 64 + u * 8 + e;
            m[e] = (gt < NT3)
                 ? Xc[uu[e] & 255] * Xc[(uu[e] >> 8) & 255] * Xc[(uu[e] >> 16) & 255]
                 : 0.f;
        }
        uint32_t h[4];
#pragma unroll
        for (int p = 0; p < 4; p++) {
            __half2 hp = __floats2half2_rn(m[2 * p], m[2 * p + 1]);
            h[p] = *(uint32_t*)&hp;
        }
        uint32_t doff = (uint32_t)(c * 128 + ((u ^ (c & 7)) << 4));
        *(uint4*)(smc + OFF_A0 + doff) = make_uint4(h[0], h[1], h[2], h[3]);
    }
    CP_WAIT0();
    __syncthreads();                       // A(q0) + B(q0) visible to all

    float acc[16][4];
#pragma unroll
    for (int nt = 0; nt < 16; nt++)
#pragma unroll
        for (int k = 0; k < 4; k++) acc[nt][k] = 0.f;

    const int rw = wid & 3, cw = wid >> 2;
    const int R0 = rw * 32, C0 = cw * 64;
    const int mat = lane >> 3, lr = lane & 7;
    const int g = lane >> 2;

    for (int i = 0, q = q0; q < q1; ++i, ++q) {
        const uint32_t bufA = (i & 1) ? OFF_A1 : OFF_A0;
        const uint32_t bufAn = (i & 1) ? OFF_A0 : OFF_A1;
        const uint32_t bufB = (i & 1) ? OFF_B1 : OFF_B0;
        const uint32_t bufBn = (i & 1) ? OFF_B0 : OFF_B1;

        if (q + 1 < q1) {
            const char* srcH = (const char*)g_B3hi + (q + 1) * 16384;
            for (int ii = tid; ii < 1024; ii += 256) {
                int row = ii >> 3, u = ii & 7;
                uint32_t doff = (uint32_t)(row * 128 + ((u ^ (row & 7)) << 4));
                int soff = (row * 64 + u * 8) * 2;
                cp16(sb + bufBn + doff, srcH + soff);
            }
            CP_COMMIT();
            // build A(q+1) into alternate buffer -- overlaps MMA(q)
            for (int item = tid; item < 1024; item += 256) {
                int c = item & 127, u = item >> 7;
                const float* Xc = Xs + c * 17;
                const uint4* ip = (const uint4*)(sIdx + (q + 1) * 64 + u * 8);
                uint4 i0 = ip[0], i1 = ip[1];
                unsigned uu[8] = {i0.x, i0.y, i0.z, i0.w, i1.x, i1.y, i1.z, i1.w};
                float m[8];
#pragma unroll
                for (int e = 0; e < 8; e++) {
                    int gt = (q + 1) * 64 + u * 8 + e;
                    m[e] = (gt < NT3)
                         ? Xc[uu[e] & 255] * Xc[(uu[e] >> 8) & 255] * Xc[(uu[e] >> 16) & 255]
                         : 0.f;
                }
                uint32_t h[4];
#pragma unroll
                for (int p = 0; p < 4; p++) {
                    __half2 hp = __floats2half2_rn(m[2 * p], m[2 * p + 1]);
                    h[p] = *(uint32_t*)&hp;
                }
                uint32_t doff = (uint32_t)(c * 128 + ((u ^ (c & 7)) << 4));
                *(uint4*)(smc + bufAn + doff) = make_uint4(h[0], h[1], h[2], h[3]);
            }
        }

        // MMA(q): 4 k-steps; warp tile 32 rows x 64 cols; single fp16 term
#pragma unroll
        for (int s = 0; s < 4; s++) {
            const int u0 = s * 2;
            uint32_t ah0[4], ah1[4];
            {
                int arow = R0 + lr + (mat & 1) * 8;
                int au = u0 + (mat >> 1);
                ldsm4(ah0, sb + bufA + (uint32_t)(arow * 128 + ((au ^ (arow & 7)) << 4)));
                int arow1 = arow + 16;
                ldsm4(ah1, sb + bufA + (uint32_t)(arow1 * 128 + ((au ^ (arow1 & 7)) << 4)));
            }
#pragma unroll
            for (int p = 0; p < 4; p++) {
                int brow = C0 + p * 16 + (mat >> 1) * 8 + lr;
                int bu = u0 + (mat & 1);
                uint32_t boff = (uint32_t)(brow * 128 + ((bu ^ (brow & 7)) << 4));
                uint32_t bh[4];
                ldsm4(bh, sb + bufB + boff);
                mma16816h(acc[p * 2],         ah0, bh[0], bh[1]);
                mma16816h(acc[p * 2 + 1],     ah0, bh[2], bh[3]);
                mma16816h(acc[8 + p * 2],     ah1, bh[0], bh[1]);
                mma16816h(acc[8 + p * 2 + 1], ah1, bh[2], bh[3]);
            }
        }
        CP_WAIT0();
        __syncthreads();   // A(q+1)/B(q+1) ready; MMA(q) done reading buffers
    }

    // ===== epilogue =====
    float* red   = (float*)(smc + OFF_A0);          // order-3 partials, 4KB
    float* red12 = (float*)(smc + OFF_A0 + 4096);   // order-1/2 partials, 4KB
    float* Us2s  = (float*)(smc + OFF_A1);          // kh==1 only, 13KB
    unsigned* sIdx2 = (unsigned*)(smc + OFF_A1 + 13056);
    const float* wyb = g_wy + b * NWY * NC;

    // kh==1: kick off staging of the order-2 table first (loads in flight)
    if (kh == 1) {
        for (int i = tid; i < NT2 * (COLS2 / 4); i += 256)
            ((float4*)Us2s)[i] = ((const float4*)g_Us2)[i];
        for (int i = tid; i < NT2; i += 256) {
            int rem = i, A = 0;
            for (;;) { int cnt = L - A; if (rem < cnt) break; rem -= cnt; A++; }
            sIdx2[i] = (unsigned)A | ((unsigned)(A + rem) << 8);
        }
    }

    // order-3: weight by wy, reduce cols (shfl) + col-groups (smem)
    float ct[4][4];
#pragma unroll
    for (int a = 0; a < 4; a++)
#pragma unroll
        for (int t = 0; t < 4; t++) ct[a][t] = 0.f;
#pragma unroll
    for (int mi = 0; mi < 2; mi++) {
        int ra = R0 + mi * 16 + g;
        int rb = ra + 8;
#pragma unroll
        for (int ni = 0; ni < 8; ni++) {
#pragma unroll
            for (int hh = 0; hh < 2; hh++) {
                int j = C0 + ni * 8 + 2 * (lane & 3) + hh;
                if (j < 122) {
                    int tgt, wyc;
                    if (j < 23) { tgt = 0; wyc = j; }
                    else { int wq = (j - 23) / 33; tgt = 1 + wq; wyc = 23 + (j - 23 - wq * 33); }
                    ct[mi * 2 + 0][tgt] += acc[mi * 8 + ni][hh]     * wyb[wyc * NC + ra];
                    ct[mi * 2 + 1][tgt] += acc[mi * 8 + ni][2 + hh] * wyb[wyc * NC + rb];
                }
            }
        }
    }
#pragma unroll
    for (int a = 0; a < 4; a++)
#pragma unroll
        for (int t = 0; t < 4; t++) {
            ct[a][t] += __shfl_xor_sync(0xffffffffu, ct[a][t], 1);
            ct[a][t] += __shfl_xor_sync(0xffffffffu, ct[a][t], 2);
        }
    if ((lane & 3) == 0) {
#pragma unroll
        for (int mi = 0; mi < 2; mi++) {
            int ra = R0 + mi * 16 + g;
#pragma unroll
            for (int t = 0; t < 4; t++) {
                red[(cw * 128 + ra) * 4 + t]     = ct[mi * 2 + 0][t];
                red[(cw * 128 + ra + 8) * 4 + t] = ct[mi * 2 + 1][t];
            }
        }
    }
    __syncthreads();    // red written; Us2s/sIdx2 staged

    // kh==1: order-2 + order-1 contribution into red12
    if (kh == 1) {
        const int c2 = tid & 127;
        const int half = tid >> 7;
        const float* Xc2 = Xs + c2 * 17;
        ull P2[11];
#pragma unroll
        for (int k = 0; k < 11; k++) P2[k] = 0ull;
        for (int t = half * 68; t < half * 68 + 68; t++) {
            unsigned u = sIdx2[t];
            ull m2 = pack2(Xc2[u & 255] * Xc2[(u >> 8) & 255]);
            const ull* row = (const ull*)(Us2s + t * COLS2);
#pragma unroll
            for (int k = 0; k < 11; k++) fma2(P2[k], m2, row[k]);
        }
        float contrib[4] = {0.f, 0.f, 0.f, 0.f};
#pragma unroll
        for (int k = 0; k < 11; k++) {
            float lo, hi;
            unpack2(P2[k], lo, hi);
#pragma unroll
            for (int hh = 0; hh < 2; hh++) {
                int j = 2 * k + hh;
                float v = (hh == 0) ? lo : hi;
                int tgt, row;
                if (j < 4) { tgt = 0; row = j; }
                else { int wq = (j - 4) / 6; tgt = 1 + wq; row = 4 + (j - 4 - wq * 6); }
                contrib[tgt] += v * wyb[(56 + row) * NC + c2];
            }
        }
        if (half == 0) {
            float P0 = 0.f, P1 = 0.f, Pq = 0.f, P3 = 0.f;
#pragma unroll
            for (int a = 0; a < L; a++) {
                float xa = Xc2[a];
                P0 = fmaf(g_Us1[a * 4 + 0], xa, P0);
                P1 = fmaf(g_Us1[a * 4 + 1], xa, P1);
                Pq = fmaf(g_Us1[a * 4 + 2], xa, Pq);
                P3 = fmaf(g_Us1[a * 4 + 3], xa, P3);
            }
            float wv66 = wyb[66 * NC + c2], wv67 = wyb[67 * NC + c2];
            contrib[0] = fmaf(P0, wv66, contrib[0]);
            contrib[1] = fmaf(P1, wv67, contrib[1]);
            contrib[2] = fmaf(Pq, wv67, contrib[2]);
            contrib[3] = fmaf(P3, wv67, contrib[3]);
        }
#pragma unroll
        for (int tgt = 0; tgt < 4; tgt++)
            red12[(c2 * 4 + tgt) * 2 + half] = contrib[tgt];
    }
    __syncthreads();

    // final: one atomicAdd per output per block (2 total, commutative)
    for (int i = tid; i < 512; i += 256) {
        int row = i >> 2, tgt = i & 3;
        float v = red[row * 4 + tgt] + red[(128 + row) * 4 + tgt];
        if (kh == 1) v += red12[i * 2] + red12[i * 2 + 1];
        float* ob = out + b * 512;
        if (tgt == 0) atomicAdd(&ob[row], v);
        else atomicAdd(&ob[128 + 3 * row + (tgt - 1)], v);
    }
}

extern "C" void kernel_launch(void* const* d_in, const int* in_sizes, int n_in,
                              void* d_out, int out_size) {
    const float* x      = (const float*)d_in[0];
    const float* y      = (const float*)d_in[1];
    const float* U1_0e  = (const float*)d_in[2];
    const float* U2_0e  = (const float*)d_in[3];
    const float* U3_0e  = (const float*)d_in[4];
    const float* U1_1o  = (const float*)d_in[5];
    const float* U2_1o  = (const float*)d_in[6];
    const float* U3_1o  = (const float*)d_in[7];
    const float* w1_0e  = (const float*)d_in[8];
    const float* w2_0e  = (const float*)d_in[9];
    const float* w3_0e  = (const float*)d_in[10];
    const float* w1_1o  = (const float*)d_in[11];
    const float* w2_1o  = (const float*)d_in[12];
    const float* w3_1o  = (const float*)d_in[13];
    float* out = (float*)d_out;

    cudaFuncSetAttribute(k_main, cudaFuncAttributeMaxDynamicSharedMemorySize, SMEM_TOTAL);

    k_pre<<<337, 512>>>(y, U1_0e, U2_0e, U3_0e, U1_1o, U2_1o, U3_1o,
                        w1_0e, w2_0e, w3_0e, w1_1o, w2_1o, w3_1o, out);
    k_main<<<2 * NB, 256, SMEM_TOTAL>>>(x, out);
}

// round 16
// speedup vs baseline: 1.2742x; 1.0822x over previous
#include <cuda_runtime.h>
#include <cuda_fp16.h>
#include <cstdint>

#define L    16
#define NB   128
#define NC   128
#define NE   10
#define NT3  816
#define NT3P 832      // padded to 13*64
#define NT2  136
#define COLS2 24
#define NWY  68
#define NCHUNK 13     // K chunks of 64

typedef unsigned long long ull;

// ---------------- device globals ----------------
__device__ __align__(16) float g_Us2[NT2 * COLS2];
__device__ float    g_Us1[L * 4];
__device__ float    g_wy[NB * NWY * NC];
// pre-swizzled fp16 coefficient chunk tiles: [chunk][16KB tile image]
__device__ __align__(16) __half g_B3[NCHUNK * 8192];
// pre-swizzled fp16 monomial chunk tiles: [b][chunk][16KB tile image]  (27.25 MB)
__device__ __align__(16) __half g_A3[NB * NCHUNK * 8192];

// ---------------- helpers ----------------
__device__ __forceinline__ uint32_t smem_u32(const void* p) {
    uint32_t a;
    asm("{ .reg .u64 t; cvta.to.shared.u64 t, %1; cvt.u32.u64 %0, t; }" : "=r"(a) : "l"(p));
    return a;
}
__device__ __forceinline__ ull pack2(float v) {
    ull r; asm("mov.b64 %0, {%1, %1};" : "=l"(r) : "f"(v)); return r;
}
__device__ __forceinline__ void unpack2(ull v, float& lo, float& hi) {
    asm("mov.b64 {%0, %1}, %2;" : "=f"(lo), "=f"(hi) : "l"(v));
}
__device__ __forceinline__ void fma2(ull& d, ull a, ull b) {
    asm("fma.rn.f32x2 %0, %1, %2, %0;" : "+l"(d) : "l"(a), "l"(b));
}
__device__ __forceinline__ void ldsm4(uint32_t* r, uint32_t addr) {
    asm volatile("ldmatrix.sync.aligned.m8n8.x4.shared.b16 {%0,%1,%2,%3}, [%4];"
                 : "=r"(r[0]), "=r"(r[1]), "=r"(r[2]), "=r"(r[3]) : "r"(addr));
}
__device__ __forceinline__ void mma16816h(float* d, const uint32_t* a,
                                          uint32_t b0, uint32_t b1) {
    asm volatile("mma.sync.aligned.m16n8k16.row.col.f32.f16.f16.f32 "
                 "{%0,%1,%2,%3}, {%4,%5,%6,%7}, {%8,%9}, {%0,%1,%2,%3};"
                 : "+f"(d[0]), "+f"(d[1]), "+f"(d[2]), "+f"(d[3])
                 : "r"(a[0]), "r"(a[1]), "r"(a[2]), "r"(a[3]), "r"(b0), "r"(b1));
}
__device__ __forceinline__ void cp16(uint32_t daddr, const void* gsrc) {
    asm volatile("cp.async.cg.shared.global [%0], [%1], 16;"
                 :: "r"(daddr), "l"(gsrc) : "memory");
}
#define CP_COMMIT() asm volatile("cp.async.commit_group;" ::: "memory")
#define CP_WAIT0()  asm volatile("cp.async.wait_group 0;" ::: "memory")

// decode sorted triple index -> packed (a | b<<8 | d<<16)
__device__ __forceinline__ unsigned decode3(int t) {
    int rem = t, A = 0, B = 0;
    {
        int i = 0;
        for (;;) { int m = L - i; int cnt = m * (m + 1) / 2;
                   if (rem < cnt) break; rem -= cnt; i++; }
        A = i;
        int q = A;
        for (;;) { int cnt = L - q;
                   if (rem < cnt) break; rem -= cnt; q++; }
        B = q;
    }
    return (unsigned)A | ((unsigned)B << 8) | ((unsigned)(B + rem) << 16);
}

// ---------------- K0: merged pre-pass ----------------
// grid = 849 x 512:
//   [0,208):   order-3 coeff symmetrize + fp16, PRE-SWIZZLED store (4 triples/blk)
//   [208,336): wy GEMM for atom b = blk-208  + zero out[b]
//   336:       order-2 symmetrized table + order-1 table
//   [337,849): monomial builder: block = (atom b, chunk-group g), 512 thr
__global__ void __launch_bounds__(512) k_pre(
        const float* __restrict__ y, const float* __restrict__ x,
        const float* __restrict__ U1_0e, const float* __restrict__ U2_0e,
        const float* __restrict__ U3_0e, const float* __restrict__ U1_1o,
        const float* __restrict__ U2_1o, const float* __restrict__ U3_1o,
        const float* __restrict__ w1_0e, const float* __restrict__ w2_0e,
        const float* __restrict__ w3_0e, const float* __restrict__ w1_1o,
        const float* __restrict__ w2_1o, const float* __restrict__ w3_1o,
        float* __restrict__ out) {
    const int blk = blockIdx.x;
    const int tid = threadIdx.x;
    if (blk < 208) {
        int t = blk * 4 + (tid >> 7);
        int j = tid & 127;
        float val = 0.f;
        if (t < NT3) {
            unsigned uu = decode3(t);
            int A = uu & 255, B = (uu >> 8) & 255, D = (uu >> 16) & 255;
            int P[6][3] = {{A,B,D},{A,D,B},{B,A,D},{B,D,A},{D,A,B},{D,B,A}};
            if (j < 122) {
                for (int i = 0; i < 6; i++) {
                    bool dup = false;
                    for (int q = 0; q < i; q++)
                        if (P[q][0] == P[i][0] && P[q][1] == P[i][1] && P[q][2] == P[i][2]) dup = true;
                    if (dup) continue;
                    int p0 = P[i][0], p1 = P[i][1], p2 = P[i][2];
                    if (j < 23) {
                        val += U3_0e[((p0 * L + p1) * L + p2) * 23 + j];
                    } else {
                        int w = (j - 23) / 33, k = (j - 23) % 33;
                        val += U3_1o[(((w * L + p0) * L + p1) * L + p2) * 33 + k];
                    }
                }
            }
        }
        if (t < NT3P) {
            int chunk = t >> 6, t_in = t & 63;
            // pre-swizzled tile position (halfs): row j, 16B unit (u ^ (j&7))
            int pos = chunk * 8192 + j * 64 + (((t_in >> 3) ^ (j & 7)) << 3) + (t_in & 7);
            g_B3[pos] = __float2half_rn(val);
        }
    } else if (blk < 336) {
        const int b = blk - 208;
        __shared__ float ys[NE];
        if (tid < NE) ys[tid] = y[b * NE + tid];
        out[b * 512 + tid] = 0.f;                    // zero base
        __syncthreads();
        for (int idx = tid; idx < NWY * NC; idx += 512) {
            int jw = idx >> 7, c = idx & 127;
            const float* wsrc; int K, k;
            if (jw < 23)       { wsrc = w3_0e; K = 23; k = jw; }
            else if (jw < 56)  { wsrc = w3_1o; K = 33; k = jw - 23; }
            else if (jw < 60)  { wsrc = w2_0e; K = 4;  k = jw - 56; }
            else if (jw < 66)  { wsrc = w2_1o; K = 6;  k = jw - 60; }
            else if (jw == 66) { wsrc = w1_0e; K = 1;  k = 0; }
            else               { wsrc = w1_1o; K = 1;  k = 0; }
            float acc = 0.f;
#pragma unroll
            for (int e = 0; e < NE; e++)
                acc = fmaf(wsrc[(e * K + k) * NC + c], ys[e], acc);
            g_wy[(b * NWY + jw) * NC + c] = acc;
        }
    } else if (blk == 336) {
        for (int i = tid; i < NT2 * COLS2; i += 512) {
            int t = i / COLS2, j = i - t * COLS2;
            int rem = t, A = 0;
            for (;;) { int cnt = L - A; if (rem < cnt) break; rem -= cnt; A++; }
            int Bp = A + rem;
            float val = 0.f;
            if (j < 22) {
                if (j < 4) {
                    val = U2_0e[(A * L + Bp) * 4 + j];
                    if (A != Bp) val += U2_0e[(Bp * L + A) * 4 + j];
                } else {
                    int w = (j - 4) / 6, k = (j - 4) % 6;
                    val = U2_1o[((w * L + A) * L + Bp) * 6 + k];
                    if (A != Bp) val += U2_1o[((w * L + Bp) * L + A) * 6 + k];
                }
            }
            g_Us2[i] = val;
        }
        if (tid < L * 4) {
            int a = tid >> 2, col = tid & 3;
            g_Us1[tid] = (col == 0) ? U1_0e[a] : U1_1o[(col - 1) * L + a];
        }
    } else {
        // ===== monomial builder =====
        __shared__ __align__(16) float Xs[NC * 17];
        __shared__ unsigned sIdx[256];
        const int bb = blk - 337;
        const int b = bb >> 2;        // atom
        const int g = bb & 3;         // chunk group (chunks g*4 .. g*4+3)
        const int cs = tid >> 7;      // chunk slot within group
        const int c = tid & 127;      // channel

        if (tid < 256) {
            int cc = tid >> 1, off = (tid & 1) * 8;
            const float4* xp = (const float4*)(x + (b * NC + cc) * L + off);
            float4 v0 = xp[0], v1 = xp[1];
            float* dst = Xs + cc * 17 + off;
            dst[0] = v0.x; dst[1] = v0.y; dst[2] = v0.z; dst[3] = v0.w;
            dst[4] = v1.x; dst[5] = v1.y; dst[6] = v1.z; dst[7] = v1.w;
        }
        if (tid < 256) {
            int t = g * 256 + tid;
            sIdx[tid] = (t < NT3) ? decode3(t) : 0u;
        }
        __syncthreads();

        const int chunk = g * 4 + cs;
        if (chunk < NCHUNK) {
            const float* Xc = Xs + c * 17;
            char* dstBase = (char*)g_A3 + (size_t)(b * NCHUNK + chunk) * 16384 + c * 128;
            const unsigned* ip = sIdx + cs * 64;
#pragma unroll
            for (int u = 0; u < 8; u++) {
                uint32_t h[4];
#pragma unroll
                for (int p = 0; p < 4; p++) {
                    unsigned u0 = ip[u * 8 + 2 * p], u1 = ip[u * 8 + 2 * p + 1];
                    float m0 = Xc[u0 & 255] * Xc[(u0 >> 8) & 255] * Xc[(u0 >> 16) & 255];
                    float m1 = Xc[u1 & 255] * Xc[(u1 >> 8) & 255] * Xc[(u1 >> 16) & 255];
                    __half2 hp = __floats2half2_rn(m0, m1);
                    h[p] = *(uint32_t*)&hp;
                }
                *(uint4*)(dstBase + ((u ^ (c & 7)) << 4)) = make_uint4(h[0], h[1], h[2], h[3]);
            }
        }
    }
}

// ---------------- K2: pure GEMM + (kh==1) order-1/2 tail ------------------
// grid = 256: (atom b, K-half kh). 8 warps = 4 row-groups x 2 col-groups.
// smem: A0 16K | A1 16K | B0 16K | B1 16K | Xs 8.5K  = 74240
#define OFF_A0   0
#define OFF_A1   16384
#define OFF_B0   32768
#define OFF_B1   49152
#define OFF_XS   65536
#define SMEM_TOTAL 74240

__global__ void __launch_bounds__(256, 2) k_main(const float* __restrict__ x,
                                                 float* __restrict__ out) {
    extern __shared__ __align__(1024) char smc[];
    const uint32_t sb = smem_u32(smc);
    const int tid = threadIdx.x;
    const int wid = tid >> 5;
    const int lane = tid & 31;
    const int b = blockIdx.x >> 1;
    const int kh = blockIdx.x & 1;
    const int q0 = kh ? 7 : 0;
    const int q1 = kh ? NCHUNK : 7;

    float* Xs = (float*)(smc + OFF_XS);
    const char* srcA = (const char*)g_A3 + (size_t)b * NCHUNK * 16384;
    const char* srcB = (const char*)g_B3;

    // prologue: linear cp.async of A(q0), B(q0); stage Xs
    for (int i = tid; i < 1024; i += 256) {
        cp16(sb + OFF_A0 + i * 16, srcA + q0 * 16384 + i * 16);
        cp16(sb + OFF_B0 + i * 16, srcB + q0 * 16384 + i * 16);
    }
    CP_COMMIT();
    {
        int c = tid >> 1, off = (tid & 1) * 8;
        const float4* xp = (const float4*)(x + (b * NC + c) * L + off);
        float4 v0 = xp[0], v1 = xp[1];
        float* dst = Xs + c * 17 + off;
        dst[0] = v0.x; dst[1] = v0.y; dst[2] = v0.z; dst[3] = v0.w;
        dst[4] = v1.x; dst[5] = v1.y; dst[6] = v1.z; dst[7] = v1.w;
    }
    CP_WAIT0();
    __syncthreads();

    float acc[16][4];
#pragma unroll
    for (int nt = 0; nt < 16; nt++)
#pragma unroll
        for (int k = 0; k < 4; k++) acc[nt][k] = 0.f;

    const int rw = wid & 3, cw = wid >> 2;
    const int R0 = rw * 32, C0 = cw * 64;
    const int mat = lane >> 3, lr = lane & 7;
    const int g = lane >> 2;

    for (int i = 0, q = q0; q < q1; ++i, ++q) {
        const uint32_t bufA = (i & 1) ? OFF_A1 : OFF_A0;
        const uint32_t bufAn = (i & 1) ? OFF_A0 : OFF_A1;
        const uint32_t bufB = (i & 1) ? OFF_B1 : OFF_B0;
        const uint32_t bufBn = (i & 1) ? OFF_B0 : OFF_B1;

        if (q + 1 < q1) {
            for (int ii = tid; ii < 1024; ii += 256) {
                cp16(sb + bufAn + ii * 16, srcA + (q + 1) * 16384 + ii * 16);
                cp16(sb + bufBn + ii * 16, srcB + (q + 1) * 16384 + ii * 16);
            }
            CP_COMMIT();
        }

        // MMA(q): 4 k-steps; warp tile 32 rows x 64 cols
#pragma unroll
        for (int s = 0; s < 4; s++) {
            const int u0 = s * 2;
            uint32_t ah0[4], ah1[4];
            {
                int arow = R0 + lr + (mat & 1) * 8;
                int au = u0 + (mat >> 1);
                ldsm4(ah0, sb + bufA + (uint32_t)(arow * 128 + ((au ^ (arow & 7)) << 4)));
                int arow1 = arow + 16;
                ldsm4(ah1, sb + bufA + (uint32_t)(arow1 * 128 + ((au ^ (arow1 & 7)) << 4)));
            }
#pragma unroll
            for (int p = 0; p < 4; p++) {
                int brow = C0 + p * 16 + (mat >> 1) * 8 + lr;
                int bu = u0 + (mat & 1);
                uint32_t boff = (uint32_t)(brow * 128 + ((bu ^ (brow & 7)) << 4));
                uint32_t bh[4];
                ldsm4(bh, sb + bufB + boff);
                mma16816h(acc[p * 2],         ah0, bh[0], bh[1]);
                mma16816h(acc[p * 2 + 1],     ah0, bh[2], bh[3]);
                mma16816h(acc[8 + p * 2],     ah1, bh[0], bh[1]);
                mma16816h(acc[8 + p * 2 + 1], ah1, bh[2], bh[3]);
            }
        }
        CP_WAIT0();
        __syncthreads();   // next buffers ready; MMA(q) done reading buffers
    }

    // ===== epilogue =====
    float* red   = (float*)(smc + OFF_A0);          // order-3 partials, 4KB
    float* red12 = (float*)(smc + OFF_A0 + 4096);   // order-1/2 partials, 4KB
    float* Us2s  = (float*)(smc + OFF_A1);          // kh==1 only, 13KB
    unsigned* sIdx2 = (unsigned*)(smc + OFF_A1 + 13056);
    const float* wyb = g_wy + b * NWY * NC;

    if (kh == 1) {
        for (int i = tid; i < NT2 * (COLS2 / 4); i += 256)
            ((float4*)Us2s)[i] = ((const float4*)g_Us2)[i];
        for (int i = tid; i < NT2; i += 256) {
            int rem = i, A = 0;
            for (;;) { int cnt = L - A; if (rem < cnt) break; rem -= cnt; A++; }
            sIdx2[i] = (unsigned)A | ((unsigned)(A + rem) << 8);
        }
    }

    // order-3: weight by wy, reduce cols (shfl) + col-groups (smem)
    float ct[4][4];
#pragma unroll
    for (int a = 0; a < 4; a++)
#pragma unroll
        for (int t = 0; t < 4; t++) ct[a][t] = 0.f;
#pragma unroll
    for (int mi = 0; mi < 2; mi++) {
        int ra = R0 + mi * 16 + g;
        int rb = ra + 8;
#pragma unroll
        for (int ni = 0; ni < 8; ni++) {
#pragma unroll
            for (int hh = 0; hh < 2; hh++) {
                int j = C0 + ni * 8 + 2 * (lane & 3) + hh;
                if (j < 122) {
                    int tgt, wyc;
                    if (j < 23) { tgt = 0; wyc = j; }
                    else { int wq = (j - 23) / 33; tgt = 1 + wq; wyc = 23 + (j - 23 - wq * 33); }
                    ct[mi * 2 + 0][tgt] += acc[mi * 8 + ni][hh]     * wyb[wyc * NC + ra];
                    ct[mi * 2 + 1][tgt] += acc[mi * 8 + ni][2 + hh] * wyb[wyc * NC + rb];
                }
            }
        }
    }
#pragma unroll
    for (int a = 0; a < 4; a++)
#pragma unroll
        for (int t = 0; t < 4; t++) {
            ct[a][t] += __shfl_xor_sync(0xffffffffu, ct[a][t], 1);
            ct[a][t] += __shfl_xor_sync(0xffffffffu, ct[a][t], 2);
        }
    if ((lane & 3) == 0) {
#pragma unroll
        for (int mi = 0; mi < 2; mi++) {
            int ra = R0 + mi * 16 + g;
#pragma unroll
            for (int t = 0; t < 4; t++) {
                red[(cw * 128 + ra) * 4 + t]     = ct[mi * 2 + 0][t];
                red[(cw * 128 + ra + 8) * 4 + t] = ct[mi * 2 + 1][t];
            }
        }
    }
    __syncthreads();

    if (kh == 1) {
        const int c2 = tid & 127;
        const int half = tid >> 7;
        const float* Xc2 = Xs + c2 * 17;
        ull P2[11];
#pragma unroll
        for (int k = 0; k < 11; k++) P2[k] = 0ull;
        for (int t = half * 68; t < half * 68 + 68; t++) {
            unsigned u = sIdx2[t];
            ull m2 = pack2(Xc2[u & 255] * Xc2[(u >> 8) & 255]);
            const ull* row = (const ull*)(Us2s + t * COLS2);
#pragma unroll
            for (int k = 0; k < 11; k++) fma2(P2[k], m2, row[k]);
        }
        float contrib[4] = {0.f, 0.f, 0.f, 0.f};
#pragma unroll
        for (int k = 0; k < 11; k++) {
            float lo, hi;
            unpack2(P2[k], lo, hi);
#pragma unroll
            for (int hh = 0; hh < 2; hh++) {
                int j = 2 * k + hh;
                float v = (hh == 0) ? lo : hi;
                int tgt, row;
                if (j < 4) { tgt = 0; row = j; }
                else { int wq = (j - 4) / 6; tgt = 1 + wq; row = 4 + (j - 4 - wq * 6); }
                contrib[tgt] += v * wyb[(56 + row) * NC + c2];
            }
        }
        if (half == 0) {
            float P0 = 0.f, P1 = 0.f, Pq = 0.f, P3 = 0.f;
#pragma unroll
            for (int a = 0; a < L; a++) {
                float xa = Xc2[a];
                P0 = fmaf(g_Us1[a * 4 + 0], xa, P0);
                P1 = fmaf(g_Us1[a * 4 + 1], xa, P1);
                Pq = fmaf(g_Us1[a * 4 + 2], xa, Pq);
                P3 = fmaf(g_Us1[a * 4 + 3], xa, P3);
            }
            float wv66 = wyb[66 * NC + c2], wv67 = wyb[67 * NC + c2];
            contrib[0] = fmaf(P0, wv66, contrib[0]);
            contrib[1] = fmaf(P1, wv67, contrib[1]);
            contrib[2] = fmaf(Pq, wv67, contrib[2]);
            contrib[3] = fmaf(P3, wv67, contrib[3]);
        }
#pragma unroll
        for (int tgt = 0; tgt < 4; tgt++)
            red12[(c2 * 4 + tgt) * 2 + half] = contrib[tgt];
    }
    __syncthreads();

    // final: one atomicAdd per output per block (2 total, commutative)
    for (int i = tid; i < 512; i += 256) {
        int row = i >> 2, tgt = i & 3;
        float v = red[row * 4 + tgt] + red[(128 + row) * 4 + tgt];
        if (kh == 1) v += red12[i * 2] + red12[i * 2 + 1];
        float* ob = out + b * 512;
        if (tgt == 0) atomicAdd(&ob[row], v);
        else atomicAdd(&ob[128 + 3 * row + (tgt - 1)], v);
    }
}

extern "C" void kernel_launch(void* const* d_in, const int* in_sizes, int n_in,
                              void* d_out, int out_size) {
    const float* x      = (const float*)d_in[0];
    const float* y      = (const float*)d_in[1];
    const float* U1_0e  = (const float*)d_in[2];
    const float* U2_0e  = (const float*)d_in[3];
    const float* U3_0e  = (const float*)d_in[4];
    const float* U1_1o  = (const float*)d_in[5];
    const float* U2_1o  = (const float*)d_in[6];
    const float* U3_1o  = (const float*)d_in[7];
    const float* w1_0e  = (const float*)d_in[8];
    const float* w2_0e  = (const float*)d_in[9];
    const float* w3_0e  = (const float*)d_in[10];
    const float* w1_1o  = (const float*)d_in[11];
    const float* w2_1o  = (const float*)d_in[12];
    const float* w3_1o  = (const float*)d_in[13];
    float* out = (float*)d_out;

    cudaFuncSetAttribute(k_main, cudaFuncAttributeMaxDynamicSharedMemorySize, SMEM_TOTAL);

    k_pre<<<849, 512>>>(y, x, U1_0e, U2_0e, U3_0e, U1_1o, U2_1o, U3_1o,
                        w1_0e, w2_0e, w3_0e, w1_1o, w2_1o, w3_1o, out);
    k_main<<<2 * NB, 256, SMEM_TOTAL>>>(x, out);
}